// round 3
// baseline (speedup 1.0000x reference)
#include <cuda_runtime.h>
#include <stdint.h>

// Problem constants (fixed by the dataset)
#define NN   10000      // nodes
#define EE   1000       // hyperedges
#define TT   29         // STEPS - 1 transition steps
#define CAP  32768      // per-step nonzero list capacity (expected ~10000)

// ---------------- device scratch (no allocations allowed) ----------------
__device__ unsigned g_cnt[TT];
__device__ unsigned g_list[TT * CAP];   // packed (e << 14) | n
__device__ float    g_y[EE];            // y = H @ infected
__device__ float    g_z[NN];            // z = H^T @ y
__device__ float    g_inf[NN];          // infected vector (0/1)
__device__ uint2    g_k1[TT];           // per-step uniform keys (u1)
__device__ uint2    g_k2[TT];           // per-step uniform keys (u2)

// ---------------- JAX Threefry-2x32 (exact replica) ----------------
__device__ __forceinline__ void tf2x32(unsigned k0, unsigned k1,
                                       unsigned x0, unsigned x1,
                                       unsigned &o0, unsigned &o1) {
    unsigned ks2 = k0 ^ k1 ^ 0x1BD11BDAu;
    x0 += k0; x1 += k1;
#define ROTL(v,d) (((v) << (d)) | ((v) >> (32 - (d))))
#define RND(r) { x0 += x1; x1 = ROTL(x1, r); x1 ^= x0; }
    RND(13) RND(15) RND(26) RND(6)
    x0 += k1;  x1 += ks2 + 1u;
    RND(17) RND(29) RND(16) RND(24)
    x0 += ks2; x1 += k0 + 2u;
    RND(13) RND(15) RND(26) RND(6)
    x0 += k0;  x1 += k1 + 3u;
    RND(17) RND(29) RND(16) RND(24)
    x0 += k1;  x1 += ks2 + 4u;
    RND(13) RND(15) RND(26) RND(6)
    x0 += ks2; x1 += k0 + 5u;
    o0 = x0; o1 = x1;
#undef RND
#undef ROTL
}

// uniform [0,1) from 32 random bits, exactly as jax.random.uniform (f32)
__device__ __forceinline__ float bits_to_uniform(unsigned bits) {
    return __uint_as_float((bits >> 9) | 0x3F800000u) - 1.0f;
}

// ---------------- init: copy t=0 rows, key chain, zero scratch ----------------
__global__ void k_init(const float* __restrict__ x, float* __restrict__ out) {
    int gid = blockIdx.x * blockDim.x + threadIdx.x;
    if (gid < NN * 3) {
        float v = x[gid];
        out[gid] = v;                                 // pathogen[0] = x
        out[(size_t)30 * NN * 3 + gid] = v;           // state[0]    = x
    }
    if (gid < NN) {
        g_z[gid]   = 0.0f;
        g_inf[gid] = x[gid * 3 + 1];
    }
    if (gid < EE) g_y[gid]   = 0.0f;
    if (gid < TT) g_cnt[gid] = 0u;
    if (gid == 0) {
        // key chain: jax.random.key(42) -> (0, 42); partitionable split:
        // key_i = threefry(key, (0, i)) full output; new carry = i=0.
        unsigned kh = 0u, kl = 42u;
        for (int t = 0; t < TT; t++) {
            unsigned a0, a1, b0, b1, c0, c1;
            tf2x32(kh, kl, 0u, 0u, a0, a1);
            tf2x32(kh, kl, 0u, 1u, b0, b1);
            tf2x32(kh, kl, 0u, 2u, c0, c1);
            g_k1[t] = make_uint2(b0, b1);
            g_k2[t] = make_uint2(c0, c1);
            kh = a0; kl = a1;
        }
    }
}

// ---------------- one full-bandwidth sweep over H: sparse extraction ----------------
// One block per (t, e) row; ballot-compacted append of nonzeros.
__global__ void k_extract(const float* __restrict__ H) {
    int b = blockIdx.x;                 // 0 .. TT*EE-1
    int t = b / EE;
    int e = b % EE;
    const float4* row = reinterpret_cast<const float4*>(H + (size_t)b * NN);
    unsigned tid  = threadIdx.x;
    unsigned lane = tid & 31u;
    unsigned ebits = (unsigned)e << 14;

    const int NITER = (NN / 4 + 127) / 128;   // 20
    for (int k = 0; k < NITER; k++) {
        int idx = k * 128 + (int)tid;
        float4 v = make_float4(0.f, 0.f, 0.f, 0.f);
        if (idx < NN / 4) v = row[idx];
        float vv[4] = {v.x, v.y, v.z, v.w};
#pragma unroll
        for (int c = 0; c < 4; c++) {
            bool nz = (vv[c] != 0.0f);
            unsigned m = __ballot_sync(0xffffffffu, nz);
            if (m == 0u) continue;
            unsigned base = 0u;
            if (lane == 0u) base = atomicAdd(&g_cnt[t], (unsigned)__popc(m));
            base = __shfl_sync(0xffffffffu, base, 0);
            if (nz) {
                unsigned off = (unsigned)__popc(m & ((1u << lane) - 1u));
                unsigned pos = base + off;
                if (pos < CAP)
                    g_list[(size_t)t * CAP + pos] = ebits | (unsigned)(idx * 4 + c);
            }
        }
    }
}

// ---------------- per-step sparse y = H @ infected ----------------
__global__ void k_spread_y(int t) {
    unsigned i = blockIdx.x * blockDim.x + threadIdx.x;
    unsigned cnt = g_cnt[t]; if (cnt > CAP) cnt = CAP;
    if (i >= cnt) return;
    unsigned p = g_list[(size_t)t * CAP + i];
    unsigned e = p >> 14, n = p & 16383u;
    float v = g_inf[n];
    if (v != 0.0f) atomicAdd(&g_y[e], v);     // integer-valued: order-exact
}

// ---------------- per-step sparse z = H^T @ y ----------------
__global__ void k_spread_z(int t) {
    unsigned i = blockIdx.x * blockDim.x + threadIdx.x;
    unsigned cnt = g_cnt[t]; if (cnt > CAP) cnt = CAP;
    if (i >= cnt) return;
    unsigned p = g_list[(size_t)t * CAP + i];
    unsigned e = p >> 14, n = p & 16383u;
    float v = g_y[e];
    if (v != 0.0f) atomicAdd(&g_z[n], v);     // integer-valued: order-exact
}

// ---------------- per-step node update (probabilities + stochastic states) ----------------
__global__ void k_node(int t,
                       const float* __restrict__ beta,
                       const float* __restrict__ gamma,
                       float* __restrict__ out) {
    int n = blockIdx.x * blockDim.x + threadIdx.x;
    if (n >= NN) return;

    float z = g_z[n];
    g_z[n] = 0.0f;                 // self-clean for next step
    if (n < EE) g_y[n] = 0.0f;     // y already consumed by k_spread_z

    const size_t PROW = (size_t)t * NN * 3 + (size_t)n * 3;           // pathogen[t]
    const size_t SROW = (size_t)(30 + t) * NN * 3 + (size_t)n * 3;    // state[t]
    float pp0 = out[PROW + 0], pp1 = out[PROW + 1], pp2 = out[PROW + 2];
    float s0  = out[SROW + 0], s1  = out[SROW + 1];

    // Exact-rounding chain, no fmad contraction (matches XLA elementwise ops)
    float nc = __fmul_rn(beta[n],  z);
    float nr = __fmul_rn(gamma[n], s1);
    float p0 = __fsub_rn(pp0, nc);
    float p1 = __fsub_rn(__fadd_rn(pp1, nc), nr);
    float p2 = __fadd_rn(pp2, nr);
    p0 = fminf(fmaxf(p0, 0.0f), 1.0f);
    p1 = fminf(fmaxf(p1, 0.0f), 1.0f);
    p2 = fminf(fmaxf(p2, 0.0f), 1.0f);

    size_t POUT = (size_t)(t + 1) * NN * 3 + (size_t)n * 3;
    out[POUT + 0] = p0; out[POUT + 1] = p1; out[POUT + 2] = p2;

    // Partitionable threefry random bits: bits[i] = o0 ^ o1 @ counter (0, i)
    uint2 k1 = g_k1[t], k2 = g_k2[t];
    unsigned o0, o1;
    tf2x32(k1.x, k1.y, 0u, (unsigned)n, o0, o1);
    float u1 = bits_to_uniform(o0 ^ o1);
    tf2x32(k2.x, k2.y, 0u, (unsigned)n, o0, o1);
    float u2 = bits_to_uniform(o0 ^ o1);

    bool wasS   = (s0 == 1.0f);
    bool wasI   = (s1 == 1.0f);
    bool s_to_I = wasS && (u1 < p1);
    bool i_ev   = wasI && (u1 < p2);
    bool i_to_R = i_ev && (u2 < 0.5f);
    bool i_to_S = i_ev && !(u2 < 0.5f);
    bool nS = (wasS && !s_to_I) || i_to_S;
    bool nI = s_to_I || (wasI && !i_ev);
    bool nR = (!wasS && !wasI) || i_to_R;

    size_t SOUT = (size_t)(30 + t + 1) * NN * 3 + (size_t)n * 3;
    float fI = nI ? 1.0f : 0.0f;
    out[SOUT + 0] = nS ? 1.0f : 0.0f;
    out[SOUT + 1] = fI;
    out[SOUT + 2] = nR ? 1.0f : 0.0f;
    g_inf[n] = fI;
}

// ---------------- launch ----------------
extern "C" void kernel_launch(void* const* d_in, const int* in_sizes, int n_in,
                              void* d_out, int out_size) {
    const float* x     = (const float*)d_in[0];  // (N,3)
    const float* H     = (const float*)d_in[1];  // (29, E, N)
    const float* beta  = (const float*)d_in[2];  // (N,)
    const float* gamma = (const float*)d_in[3];  // (N,)
    float* out = (float*)d_out;                  // pathogen (30,N,3) then state (30,N,3)

    (void)in_sizes; (void)n_in; (void)out_size;

    k_init<<<(NN * 3 + 127) / 128, 128>>>(x, out);
    k_extract<<<TT * EE, 128>>>(H);
    for (int t = 0; t < TT; t++) {
        k_spread_y<<<CAP / 256, 256>>>(t);
        k_spread_z<<<CAP / 256, 256>>>(t);
        k_node<<<(NN + 127) / 128, 128>>>(t, beta, gamma, out);
    }
}

// round 4
// speedup vs baseline: 1.0602x; 1.0602x over previous
#include <cuda_runtime.h>
#include <stdint.h>

// Problem constants (fixed by the dataset)
#define NN    10000      // nodes
#define EE    1000       // hyperedges
#define TT    29         // STEPS - 1 transition steps
#define CAP   32768      // per-step nonzero list capacity (expected ~10000)
#define NBLK  148        // persistent grid (<= SM count, guaranteed co-resident)
#define NSIM  16         // blocks dedicated to the sequential simulation
#define TPB   256        // threads per block
#define ROWF4 (NN / 4)   // 2500 float4 per H row
#define PFD   10         // float4 prefetch depth per thread (10*256 >= 2500)

// ---------------- device scratch (no allocations allowed) ----------------
__device__ unsigned g_cnt[TT];
__device__ unsigned g_list[TT * CAP];   // packed (e << 14) | n
__device__ float    g_y[EE];            // y = H @ infected
__device__ float    g_z[NN];            // z = H^T @ y
__device__ float    g_inf[NN];          // infected vector (0/1)
__device__ uint2    g_k1[TT];           // per-step uniform keys (u1)
__device__ uint2    g_k2[TT];           // per-step uniform keys (u2)
__device__ unsigned g_rows_done[TT];    // extraction progress per step (release flag)
__device__ unsigned g_work;             // extraction row work counter
__device__ unsigned g_bar_cnt;          // sim grid barrier: arrivals (monotonic)
__device__ unsigned g_bar_gen;          // sim grid barrier: released generation

// ---------------- JAX Threefry-2x32 (exact replica) ----------------
__device__ __forceinline__ void tf2x32(unsigned k0, unsigned k1,
                                       unsigned x0, unsigned x1,
                                       unsigned &o0, unsigned &o1) {
    unsigned ks2 = k0 ^ k1 ^ 0x1BD11BDAu;
    x0 += k0; x1 += k1;
#define ROTL(v,d) (((v) << (d)) | ((v) >> (32 - (d))))
#define RND(r) { x0 += x1; x1 = ROTL(x1, r); x1 ^= x0; }
    RND(13) RND(15) RND(26) RND(6)
    x0 += k1;  x1 += ks2 + 1u;
    RND(17) RND(29) RND(16) RND(24)
    x0 += ks2; x1 += k0 + 2u;
    RND(13) RND(15) RND(26) RND(6)
    x0 += k0;  x1 += k1 + 3u;
    RND(17) RND(29) RND(16) RND(24)
    x0 += k1;  x1 += ks2 + 4u;
    RND(13) RND(15) RND(26) RND(6)
    x0 += ks2; x1 += k0 + 5u;
    o0 = x0; o1 = x1;
#undef RND
#undef ROTL
}

__device__ __forceinline__ float bits_to_uniform(unsigned bits) {
    return __uint_as_float((bits >> 9) | 0x3F800000u) - 1.0f;
}

// ---------------- init: copy t=0 rows, key chain, reset all scratch ----------------
__global__ void k_init(const float* __restrict__ x, float* __restrict__ out) {
    int gid = blockIdx.x * blockDim.x + threadIdx.x;
    if (gid < NN * 3) {
        float v = x[gid];
        out[gid] = v;                                 // pathogen[0] = x
        out[(size_t)30 * NN * 3 + gid] = v;           // state[0]    = x
    }
    if (gid < NN) {
        g_z[gid]   = 0.0f;
        g_inf[gid] = x[gid * 3 + 1];
    }
    if (gid < EE) g_y[gid] = 0.0f;
    if (gid < TT) { g_cnt[gid] = 0u; g_rows_done[gid] = 0u; }
    if (gid == 0) {
        g_work = 0u; g_bar_cnt = 0u; g_bar_gen = 0u;
        // key chain: jax.random.key(42) -> (0, 42); partitionable split:
        // key_i = threefry(key, (0, i)) full output; new carry = i=0.
        unsigned kh = 0u, kl = 42u;
        for (int t = 0; t < TT; t++) {
            unsigned a0, a1, b0, b1, c0, c1;
            tf2x32(kh, kl, 0u, 0u, a0, a1);
            tf2x32(kh, kl, 0u, 1u, b0, b1);
            tf2x32(kh, kl, 0u, 2u, c0, c1);
            g_k1[t] = make_uint2(b0, b1);
            g_k2[t] = make_uint2(c0, c1);
            kh = a0; kl = a1;
        }
    }
}

// ---------------- sim-side grid barrier (NSIM blocks, sense counting) ----------------
__device__ __forceinline__ void sim_barrier(unsigned &gen) {
    __syncthreads();
    gen += 1u;
    if (threadIdx.x == 0) {
        __threadfence();                                   // release my writes
        unsigned a = atomicAdd(&g_bar_cnt, 1u) + 1u;
        if (a == gen * NSIM) {
            atomicExch(&g_bar_gen, gen);                   // release generation
        } else {
            while (atomicAdd(&g_bar_gen, 0u) < gen) __nanosleep(64);
        }
        __threadfence();                                   // acquire others' writes
    }
    __syncthreads();
}

// ---------------- producer role: stream H, build sparse lists ----------------
__device__ void do_extract(const float* __restrict__ H) {
    __shared__ unsigned s_row;
    const int tid = threadIdx.x;
    const unsigned lane = (unsigned)tid & 31u;

    for (;;) {
        if (tid == 0) s_row = atomicAdd(&g_work, 1u);
        __syncthreads();
        unsigned r = s_row;
        if (r >= (unsigned)(TT * EE)) return;

        unsigned t = r / EE, e = r % EE;
        unsigned ebits = e << 14;
        const float4* row = reinterpret_cast<const float4*>(H + (size_t)r * NN);

        // Prefetch the whole per-thread slice first: MLP = PFD per thread,
        // 40KB in flight per SM -> LTS/HBM bound, not latency bound.
        float4 buf[PFD];
#pragma unroll
        for (int k = 0; k < PFD; k++) {
            int idx = k * TPB + tid;
            buf[k] = (idx < ROWF4) ? __ldg(row + idx)
                                   : make_float4(0.f, 0.f, 0.f, 0.f);
        }

#pragma unroll
        for (int k = 0; k < PFD; k++) {
            float4 v = buf[k];
            bool any = (v.x != 0.f) | (v.y != 0.f) | (v.z != 0.f) | (v.w != 0.f);
            if (__ballot_sync(0xffffffffu, any) == 0u) continue;  // ~88% of quads
            int base4 = (k * TPB + tid) * 4;
            float vv[4] = {v.x, v.y, v.z, v.w};
#pragma unroll
            for (int c = 0; c < 4; c++) {
                bool nz = (vv[c] != 0.0f);
                unsigned m = __ballot_sync(0xffffffffu, nz);
                if (m == 0u) continue;
                unsigned base = 0u;
                if (lane == 0u) base = atomicAdd(&g_cnt[t], (unsigned)__popc(m));
                base = __shfl_sync(0xffffffffu, base, 0);
                if (nz) {
                    unsigned pos = base + (unsigned)__popc(m & ((1u << lane) - 1u));
                    if (pos < CAP)
                        g_list[(size_t)t * CAP + pos] = ebits | (unsigned)(base4 + c);
                }
            }
        }

        __threadfence();        // all threads: order list writes before done flag
        __syncthreads();
        if (tid == 0) atomicAdd(&g_rows_done[t], 1u);   // release step-t progress
    }
}

// ---------------- consumer role: 29 sequential SIR steps ----------------
__device__ void do_sim(const float* __restrict__ beta,
                       const float* __restrict__ gamma,
                       float* __restrict__ out) {
    const int tid  = threadIdx.x;
    const int gidx = blockIdx.x * TPB + tid;     // 0 .. NSIM*TPB-1
    const int GS   = NSIM * TPB;
    unsigned gen = 0;

    for (int t = 0; t < TT; t++) {
        // wait until extraction finished all EE rows of step t
        if (tid == 0) {
            while (atomicAdd(&g_rows_done[t], 0u) < (unsigned)EE) __nanosleep(256);
        }
        __syncthreads();
        __threadfence();                         // acquire list writes

        unsigned cnt = g_cnt[t]; if (cnt > CAP) cnt = CAP;
        const unsigned* lst = g_list + (size_t)t * CAP;

        // phase 1: y = H @ infected  (integer-valued, order-exact atomics)
        for (unsigned i = (unsigned)gidx; i < cnt; i += GS) {
            unsigned p = lst[i];
            float v = g_inf[p & 16383u];
            if (v != 0.0f) atomicAdd(&g_y[p >> 14], v);
        }
        sim_barrier(gen);

        // phase 2: z = H^T @ y
        for (unsigned i = (unsigned)gidx; i < cnt; i += GS) {
            unsigned p = lst[i];
            float v = g_y[p >> 14];
            if (v != 0.0f) atomicAdd(&g_z[p & 16383u], v);
        }
        sim_barrier(gen);

        // phase 3: node update (probabilities + stochastic state machine)
        for (int n = gidx; n < NN; n += GS) {
            float z = g_z[n];
            g_z[n] = 0.0f;
            if (n < EE) g_y[n] = 0.0f;

            const size_t PROW = (size_t)t * NN * 3 + (size_t)n * 3;
            const size_t SROW = (size_t)(30 + t) * NN * 3 + (size_t)n * 3;
            float pp0 = out[PROW + 0], pp1 = out[PROW + 1], pp2 = out[PROW + 2];
            float s0  = out[SROW + 0], s1  = out[SROW + 1];

            // Exact-rounding chain, no fmad contraction (matches XLA)
            float nc = __fmul_rn(beta[n],  z);
            float nr = __fmul_rn(gamma[n], s1);
            float p0 = __fsub_rn(pp0, nc);
            float p1 = __fsub_rn(__fadd_rn(pp1, nc), nr);
            float p2 = __fadd_rn(pp2, nr);
            p0 = fminf(fmaxf(p0, 0.0f), 1.0f);
            p1 = fminf(fmaxf(p1, 0.0f), 1.0f);
            p2 = fminf(fmaxf(p2, 0.0f), 1.0f);

            size_t POUT = (size_t)(t + 1) * NN * 3 + (size_t)n * 3;
            out[POUT + 0] = p0; out[POUT + 1] = p1; out[POUT + 2] = p2;

            uint2 k1 = g_k1[t], k2 = g_k2[t];
            unsigned o0, o1;
            tf2x32(k1.x, k1.y, 0u, (unsigned)n, o0, o1);
            float u1 = bits_to_uniform(o0 ^ o1);
            tf2x32(k2.x, k2.y, 0u, (unsigned)n, o0, o1);
            float u2 = bits_to_uniform(o0 ^ o1);

            bool wasS   = (s0 == 1.0f);
            bool wasI   = (s1 == 1.0f);
            bool s_to_I = wasS && (u1 < p1);
            bool i_ev   = wasI && (u1 < p2);
            bool i_to_R = i_ev && (u2 < 0.5f);
            bool i_to_S = i_ev && !(u2 < 0.5f);
            bool nS = (wasS && !s_to_I) || i_to_S;
            bool nI = s_to_I || (wasI && !i_ev);
            bool nR = (!wasS && !wasI) || i_to_R;

            size_t SOUT = (size_t)(30 + t + 1) * NN * 3 + (size_t)n * 3;
            float fI = nI ? 1.0f : 0.0f;
            out[SOUT + 0] = nS ? 1.0f : 0.0f;
            out[SOUT + 1] = fI;
            out[SOUT + 2] = nR ? 1.0f : 0.0f;
            g_inf[n] = fI;
        }
        sim_barrier(gen);   // inf/p/s visible before next step's phase 1
    }
}

// ---------------- fused persistent kernel: overlap extraction with simulation ----
__global__ void __launch_bounds__(TPB, 1)
k_fused(const float* __restrict__ H,
        const float* __restrict__ beta,
        const float* __restrict__ gamma,
        float* __restrict__ out) {
    if (blockIdx.x < NSIM) do_sim(beta, gamma, out);
    else                   do_extract(H);
}

// ---------------- launch ----------------
extern "C" void kernel_launch(void* const* d_in, const int* in_sizes, int n_in,
                              void* d_out, int out_size) {
    const float* x     = (const float*)d_in[0];  // (N,3)
    const float* H     = (const float*)d_in[1];  // (29, E, N)
    const float* beta  = (const float*)d_in[2];  // (N,)
    const float* gamma = (const float*)d_in[3];  // (N,)
    float* out = (float*)d_out;                  // pathogen (30,N,3) then state (30,N,3)

    (void)in_sizes; (void)n_in; (void)out_size;

    k_init<<<(NN * 3 + 127) / 128, 128>>>(x, out);
    k_fused<<<NBLK, TPB>>>(H, beta, gamma, out);
}

// round 6
// speedup vs baseline: 1.6251x; 1.5329x over previous
#include <cuda_runtime.h>
#include <stdint.h>

// Problem constants (fixed by the dataset)
#define NN     10000      // nodes
#define EE     1000       // hyperedges
#define TT     29         // STEPS - 1 transition steps
#define ROWCAP 64         // per-row nonzero capacity (Binom(10000,0.001): P(>64)~0)
#define GRAB   4          // rows grabbed per global atomic
#define NSIM   16         // blocks dedicated to the sequential simulation
#define NBLK   (NSIM + 264) // 2 extraction blocks per SM + sim blocks
#define TPB    256
#define ROWF4  (NN / 4)   // 2500 float4 per H row
#define PFD    10         // float4 per thread per row (10*256 >= 2500)

// ---------------- device scratch (no allocations allowed) ----------------
__device__ unsigned short g_list[(size_t)TT * EE * ROWCAP]; // node ids per row
__device__ unsigned g_rowcnt[TT * EE]; // nonzeros per row
__device__ float    g_z[NN];           // z = H^T (H @ infected)
__device__ float    g_inf[NN];         // infected vector (0/1)
__device__ uint2    g_k1[TT];          // per-step uniform keys (u1)
__device__ uint2    g_k2[TT];          // per-step uniform keys (u2)
__device__ unsigned g_rows_done[TT];   // extraction progress per step (release flag)
__device__ unsigned g_work;            // extraction row work counter
__device__ unsigned g_bar_cnt;         // sim grid barrier: arrivals (monotonic)
__device__ unsigned g_bar_gen;         // sim grid barrier: released generation

// ---------------- JAX Threefry-2x32 (exact replica) ----------------
__device__ __forceinline__ void tf2x32(unsigned k0, unsigned k1,
                                       unsigned x0, unsigned x1,
                                       unsigned &o0, unsigned &o1) {
    unsigned ks2 = k0 ^ k1 ^ 0x1BD11BDAu;
    x0 += k0; x1 += k1;
#define ROTL(v,d) (((v) << (d)) | ((v) >> (32 - (d))))
#define RND(r) { x0 += x1; x1 = ROTL(x1, r); x1 ^= x0; }
    RND(13) RND(15) RND(26) RND(6)
    x0 += k1;  x1 += ks2 + 1u;
    RND(17) RND(29) RND(16) RND(24)
    x0 += ks2; x1 += k0 + 2u;
    RND(13) RND(15) RND(26) RND(6)
    x0 += k0;  x1 += k1 + 3u;
    RND(17) RND(29) RND(16) RND(24)
    x0 += k1;  x1 += ks2 + 4u;
    RND(13) RND(15) RND(26) RND(6)
    x0 += ks2; x1 += k0 + 5u;
    o0 = x0; o1 = x1;
#undef RND
#undef ROTL
}

__device__ __forceinline__ float bits_to_uniform(unsigned bits) {
    return __uint_as_float((bits >> 9) | 0x3F800000u) - 1.0f;
}

// ---------------- init: copy t=0 rows, key chain, reset all scratch ----------------
__global__ void k_init(const float* __restrict__ x, float* __restrict__ out) {
    int gid = blockIdx.x * blockDim.x + threadIdx.x;
    if (gid < NN * 3) {
        float v = x[gid];
        out[gid] = v;                                 // pathogen[0] = x
        out[(size_t)30 * NN * 3 + gid] = v;           // state[0]    = x
    }
    if (gid < NN) {
        g_z[gid]   = 0.0f;
        g_inf[gid] = x[gid * 3 + 1];
    }
    if (gid < TT) g_rows_done[gid] = 0u;
    if (gid == 0) {
        g_work = 0u; g_bar_cnt = 0u; g_bar_gen = 0u;
        // key chain: jax.random.key(42) -> (0, 42); partitionable split:
        // key_i = threefry(key, (0, i)) full output; new carry = i=0.
        unsigned kh = 0u, kl = 42u;
        for (int t = 0; t < TT; t++) {
            unsigned a0, a1, b0, b1, c0, c1;
            tf2x32(kh, kl, 0u, 0u, a0, a1);
            tf2x32(kh, kl, 0u, 1u, b0, b1);
            tf2x32(kh, kl, 0u, 2u, c0, c1);
            g_k1[t] = make_uint2(b0, b1);
            g_k2[t] = make_uint2(c0, c1);
            kh = a0; kl = a1;
        }
    }
}

// ---------------- sim-side grid barrier (NSIM blocks, sense counting) ----------------
__device__ __forceinline__ void sim_barrier(unsigned &gen) {
    __syncthreads();
    gen += 1u;
    if (threadIdx.x == 0) {
        __threadfence();                                   // release my writes
        unsigned a = atomicAdd(&g_bar_cnt, 1u) + 1u;
        if (a == gen * NSIM) {
            atomicExch(&g_bar_gen, gen);                   // release generation
        } else {
            while (atomicAdd(&g_bar_gen, 0u) < gen) __nanosleep(64);
        }
        __threadfence();                                   // acquire others' writes
    }
    __syncthreads();
}

// ---------------- producer role: stream H, build per-row sparse slot lists ------
// Per-row private slot region => only SHARED-memory counters; no global
// counter contention. One global work-grab atomic per GRAB rows.
__device__ void do_extract(const float* __restrict__ H) {
    __shared__ unsigned s_base;
    __shared__ unsigned s_cnt;
    const int tid = threadIdx.x;
    const unsigned lane = (unsigned)tid & 31u;

    for (;;) {
        if (tid == 0) s_base = atomicAdd(&g_work, GRAB);
        __syncthreads();
        unsigned base = s_base;
        if (base >= (unsigned)(TT * EE)) return;
        unsigned lim = base + GRAB;
        if (lim > (unsigned)(TT * EE)) lim = TT * EE;

        for (unsigned r = base; r < lim; r++) {
            if (tid == 0) s_cnt = 0u;
            const float4* row = reinterpret_cast<const float4*>(H + (size_t)r * NN);

            // Front-batched load of the whole per-thread slice: MLP=10/thread,
            // 2 blocks/SM -> 80KB in flight per SM (>> latency-hiding need).
            float4 buf[PFD];
#pragma unroll
            for (int k = 0; k < PFD; k++) {
                int idx = k * TPB + tid;
                buf[k] = (idx < ROWF4) ? __ldg(row + idx)
                                       : make_float4(0.f, 0.f, 0.f, 0.f);
            }
            __syncthreads();   // s_cnt reset visible (overlaps load latency)

            unsigned short* lp = g_list + (size_t)r * ROWCAP;
#pragma unroll
            for (int k = 0; k < PFD; k++) {
                float4 v = buf[k];
                bool any = (v.x != 0.f) | (v.y != 0.f) | (v.z != 0.f) | (v.w != 0.f);
                if (__ballot_sync(0xffffffffu, any) == 0u) continue;  // ~88% skip
                int base4 = (k * TPB + tid) * 4;
                float vv[4] = {v.x, v.y, v.z, v.w};
#pragma unroll
                for (int c = 0; c < 4; c++) {
                    bool nz = (vv[c] != 0.0f);
                    unsigned m = __ballot_sync(0xffffffffu, nz);
                    if (m == 0u) continue;
                    unsigned wbase = 0u;
                    if (lane == 0u) wbase = atomicAdd(&s_cnt, (unsigned)__popc(m));
                    wbase = __shfl_sync(0xffffffffu, wbase, 0);
                    if (nz) {
                        unsigned pos = wbase + (unsigned)__popc(m & ((1u << lane) - 1u));
                        if (pos < ROWCAP)
                            lp[pos] = (unsigned short)(base4 + c);
                    }
                }
            }

            __threadfence();        // all threads: order slot writes
            __syncthreads();        // s_cnt final
            if (tid == 0) {
                unsigned c = s_cnt; if (c > ROWCAP) c = ROWCAP;
                g_rowcnt[r] = c;
                __threadfence();
                atomicAdd(&g_rows_done[r / EE], 1u);   // release step progress
            }
        }
    }
}

// ---------------- consumer role: 29 sequential SIR steps ----------------
__device__ void do_sim(const float* __restrict__ beta,
                       const float* __restrict__ gamma,
                       float* __restrict__ out) {
    const int tid  = threadIdx.x;
    const int gidx = blockIdx.x * TPB + tid;     // 0 .. NSIM*TPB-1
    const int GS   = NSIM * TPB;
    unsigned gen = 0;

    for (int t = 0; t < TT; t++) {
        // wait until extraction finished all EE rows of step t
        if (tid == 0) {
            while (atomicAdd(&g_rows_done[t], 0u) < (unsigned)EE) __nanosleep(256);
        }
        __syncthreads();
        __threadfence();                         // acquire list writes

        // phase A (fused SpMV pair): per row e,
        //   y_e = sum_{n in row} inf[n];  then z[n] += y_e for each n in row.
        // All values integer-valued in fp32 -> atomic order exact.
        for (int e = gidx; e < EE; e += GS) {
            unsigned r = (unsigned)t * EE + (unsigned)e;
            unsigned c = g_rowcnt[r];
            const unsigned short* lp = g_list + (size_t)r * ROWCAP;
            float ysum = 0.0f;
            for (unsigned i = 0; i < c; i++) ysum += g_inf[lp[i]];
            if (ysum != 0.0f)
                for (unsigned i = 0; i < c; i++) atomicAdd(&g_z[lp[i]], ysum);
        }
        sim_barrier(gen);

        // phase B: node update (probabilities + stochastic state machine)
        for (int n = gidx; n < NN; n += GS) {
            float z = g_z[n];
            g_z[n] = 0.0f;

            const size_t PROW = (size_t)t * NN * 3 + (size_t)n * 3;
            const size_t SROW = (size_t)(30 + t) * NN * 3 + (size_t)n * 3;
            float pp0 = out[PROW + 0], pp1 = out[PROW + 1], pp2 = out[PROW + 2];
            float s0  = out[SROW + 0], s1  = out[SROW + 1];

            // Exact-rounding chain, no fmad contraction (matches XLA)
            float nc = __fmul_rn(beta[n],  z);
            float nr = __fmul_rn(gamma[n], s1);
            float p0 = __fsub_rn(pp0, nc);
            float p1 = __fsub_rn(__fadd_rn(pp1, nc), nr);
            float p2 = __fadd_rn(pp2, nr);
            p0 = fminf(fmaxf(p0, 0.0f), 1.0f);
            p1 = fminf(fmaxf(p1, 0.0f), 1.0f);
            p2 = fminf(fmaxf(p2, 0.0f), 1.0f);

            size_t POUT = (size_t)(t + 1) * NN * 3 + (size_t)n * 3;
            out[POUT + 0] = p0; out[POUT + 1] = p1; out[POUT + 2] = p2;

            uint2 k1 = g_k1[t], k2 = g_k2[t];
            unsigned o0, o1;
            tf2x32(k1.x, k1.y, 0u, (unsigned)n, o0, o1);
            float u1 = bits_to_uniform(o0 ^ o1);
            tf2x32(k2.x, k2.y, 0u, (unsigned)n, o0, o1);
            float u2 = bits_to_uniform(o0 ^ o1);

            bool wasS   = (s0 == 1.0f);
            bool wasI   = (s1 == 1.0f);
            bool s_to_I = wasS && (u1 < p1);
            bool i_ev   = wasI && (u1 < p2);
            bool i_to_R = i_ev && (u2 < 0.5f);
            bool i_to_S = i_ev && !(u2 < 0.5f);
            bool nS = (wasS && !s_to_I) || i_to_S;
            bool nI = s_to_I || (wasI && !i_ev);
            bool nR = (!wasS && !wasI) || i_to_R;

            size_t SOUT = (size_t)(30 + t + 1) * NN * 3 + (size_t)n * 3;
            float fI = nI ? 1.0f : 0.0f;
            out[SOUT + 0] = nS ? 1.0f : 0.0f;
            out[SOUT + 1] = fI;
            out[SOUT + 2] = nR ? 1.0f : 0.0f;
            g_inf[n] = fI;
        }
        sim_barrier(gen);   // inf/z visible before next step's phase A
    }
}

// ---------------- fused persistent kernel: overlap extraction with simulation ----
// Sim blocks are bids 0..NSIM-1 (scheduled first => guaranteed resident).
// Extraction blocks never wait on sim, so stragglers can't deadlock.
__global__ void __launch_bounds__(TPB, 2)
k_fused(const float* __restrict__ H,
        const float* __restrict__ beta,
        const float* __restrict__ gamma,
        float* __restrict__ out) {
    if (blockIdx.x < NSIM) do_sim(beta, gamma, out);
    else                   do_extract(H);
}

// ---------------- launch ----------------
extern "C" void kernel_launch(void* const* d_in, const int* in_sizes, int n_in,
                              void* d_out, int out_size) {
    const float* x     = (const float*)d_in[0];  // (N,3)
    const float* H     = (const float*)d_in[1];  // (29, E, N)
    const float* beta  = (const float*)d_in[2];  // (N,)
    const float* gamma = (const float*)d_in[3];  // (N,)
    float* out = (float*)d_out;                  // pathogen (30,N,3) then state (30,N,3)

    (void)in_sizes; (void)n_in; (void)out_size;

    k_init<<<(NN * 3 + 127) / 128, 128>>>(x, out);
    k_fused<<<NBLK, TPB>>>(H, beta, gamma, out);
}